// round 9
// baseline (speedup 1.0000x reference)
#include <cuda_runtime.h>
#include <math.h>

#define NN 50000
#define NE 800000
#define HD 256

// ---------------- device scratch (no dynamic allocation allowed) ----------------
__device__ __align__(16) float g_agg[NN * HD];    // 51.2 MB  aggregated neighbor means
__device__ __align__(16) float g_h1[NN * HD];     // 51.2 MB  layer-1 output
__device__ __align__(16) float g_h2[NN * HD];     // 51.2 MB  layer-2 output
__device__ __align__(16) float g_WT[6 * HD * HD]; // 1.5 MB   WT[k][j] = W[j][k]
__device__ int   g_count[NN];
__device__ int   g_fill[NN];
__device__ int   g_rowptr[NN + 1];
__device__ int   g_col[NE];
__device__ int   g_is64;                          // edge_index dtype flag (sniffed)

// ---------------- small helpers ----------------
__device__ __forceinline__ void acc4(float4& a, const float4 b) {
    a.x += b.x; a.y += b.y; a.z += b.z; a.w += b.w;
}

__device__ __forceinline__ float elu1(float v) {
    return (v > 0.0f) ? v : expm1f(v);
}

// read edge endpoint idx (0..2*NE-1) honoring sniffed dtype
__device__ __forceinline__ int edge_at(const void* ei, int idx, int is64) {
    if (is64) return (int)((const long long*)ei)[idx];
    return ((const int*)ei)[idx];
}

// ---------------- dtype sniff ----------------
// int64 little-endian with values < 2^31: every odd 32-bit word is 0.
// int32: odd words are random node ids -> essentially never all zero.
__global__ void k_sniff(const void* ei) {
    const int* w = (const int*)ei;
    int odd_nonzero = 0;
    for (int i = 1; i < 256; i += 2) odd_nonzero |= (w[i] != 0);
    g_is64 = odd_nonzero ? 0 : 1;
}

// ---------------- CSR construction ----------------
__global__ void k_zero_counts() {
    int i = blockIdx.x * blockDim.x + threadIdx.x;
    if (i < NN) { g_count[i] = 0; g_fill[i] = 0; }
}

__global__ void k_transpose(const float* __restrict__ W, int slot) {
    int t = blockIdx.x * blockDim.x + threadIdx.x;
    if (t < HD * HD) {
        int k = t / HD, j = t % HD;
        g_WT[slot * HD * HD + t] = W[j * HD + k];   // coalesced write
    }
}

__global__ void k_hist(const void* __restrict__ ei) {
    int e = blockIdx.x * blockDim.x + threadIdx.x;
    if (e < NE) {
        int dst = edge_at(ei, NE + e, g_is64);
        if ((unsigned)dst < NN) atomicAdd(&g_count[dst], 1);
    }
}

// single-block exclusive scan over 50000 degree counts
__global__ void k_scan() {
    __shared__ int s[1024];
    int tid = threadIdx.x;
    const int chunk = (NN + 1023) / 1024;   // 49
    int start = tid * chunk;
    int end = min(start + chunk, NN);
    int sum = 0;
    for (int i = start; i < end; i++) sum += g_count[i];
    s[tid] = sum;
    __syncthreads();
    for (int off = 1; off < 1024; off <<= 1) {
        int v = 0;
        if (tid >= off) v = s[tid - off];
        __syncthreads();
        if (tid >= off) s[tid] += v;
        __syncthreads();
    }
    int run = (tid > 0) ? s[tid - 1] : 0;   // exclusive base
    for (int i = start; i < end; i++) { g_rowptr[i] = run; run += g_count[i]; }
    if (tid == 0) g_rowptr[NN] = NE;
}

__global__ void k_scatter(const void* __restrict__ ei) {
    int e = blockIdx.x * blockDim.x + threadIdx.x;
    if (e < NE) {
        int is64 = g_is64;
        int dst = edge_at(ei, NE + e, is64);
        int src = edge_at(ei, e, is64);
        if ((unsigned)dst < NN && (unsigned)src < NN) {
            int pos = g_rowptr[dst] + atomicAdd(&g_fill[dst], 1);
            g_col[pos] = src;
        }
    }
}

// ---------------- neighbor mean aggregation: one warp per node ----------------
// sel: 0 -> external x, 1 -> g_h1, 2 -> g_h2
__global__ void k_aggregate(const float* __restrict__ xext, int sel) {
    const float* __restrict__ xin = (sel == 0) ? xext : (sel == 1 ? g_h1 : g_h2);
    int gw = (blockIdx.x * blockDim.x + threadIdx.x) >> 5;
    int lane = threadIdx.x & 31;
    if (gw >= NN) return;

    int beg = g_rowptr[gw], end = g_rowptr[gw + 1];
    float4 a0 = make_float4(0.f, 0.f, 0.f, 0.f);
    float4 a1 = make_float4(0.f, 0.f, 0.f, 0.f);

    int i = beg;
    for (; i + 1 < end; i += 2) {                 // unroll x2 for MLP
        int n0 = g_col[i];
        int n1 = g_col[i + 1];
        const float4* r0 = (const float4*)(xin + (size_t)n0 * HD);
        const float4* r1 = (const float4*)(xin + (size_t)n1 * HD);
        float4 v0 = r0[lane];
        float4 v1 = r0[lane + 32];
        float4 w0 = r1[lane];
        float4 w1 = r1[lane + 32];
        acc4(a0, v0); acc4(a0, w0);
        acc4(a1, v1); acc4(a1, w1);
    }
    if (i < end) {
        int n0 = g_col[i];
        const float4* r0 = (const float4*)(xin + (size_t)n0 * HD);
        acc4(a0, r0[lane]);
        acc4(a1, r0[lane + 32]);
    }

    float inv = 1.0f / fmaxf((float)(end - beg), 1.0f);
    a0.x *= inv; a0.y *= inv; a0.z *= inv; a0.w *= inv;
    a1.x *= inv; a1.y *= inv; a1.z *= inv; a1.w *= inv;

    float4* dst = (float4*)(g_agg + (size_t)gw * HD);
    dst[lane]      = a0;
    dst[lane + 32] = a1;
}

// ---------------- fused dual GEMM + bias + ELU ----------------
// out[n][j] = ELU( sum_k agg[n][k]*Wl[j][k] + sum_k x[n][k]*Wr[j][k] + bl[j] )
// Tile 128(M) x 128(N) x 16(K), 256 threads, 8x8 microtile per thread, both GEMMs fused.
__global__ void __launch_bounds__(256, 2)
k_gemm_elu(const float* __restrict__ xext, int insel,
           int wslot, const float* __restrict__ bias,
           float* __restrict__ oext, int outsel)
{
    const float* __restrict__ Ax  = (insel == 0) ? xext : (insel == 1 ? g_h1 : g_h2);
    float* __restrict__ out       = (outsel == 0) ? oext : (outsel == 1 ? g_h1 : g_h2);
    const float* __restrict__ WlT = g_WT + (size_t)wslot * HD * HD;
    const float* __restrict__ WrT = g_WT + (size_t)(wslot + 1) * HD * HD;

    __shared__ float Aa_s[128 * 20];   // stride 20 keeps 16B alignment, kills bank conflicts
    __shared__ float Ax_s[128 * 20];
    __shared__ float Wl_s[16 * 128];
    __shared__ float Wr_s[16 * 128];

    int tid = threadIdx.x;
    int tx = tid & 15;
    int ty = tid >> 4;
    int mbase = blockIdx.x * 128;
    int jb = blockIdx.y * 128;

    float acc[8][8];
#pragma unroll
    for (int i = 0; i < 8; i++)
#pragma unroll
        for (int j = 0; j < 8; j++) acc[i][j] = 0.0f;

    for (int kb = 0; kb < HD; kb += 16) {
        // --- load A tiles (both matrices), bounds-guarded ---
#pragma unroll
        for (int p = 0; p < 2; p++) {
            int t = tid + p * 256;          // 0..511 float4 slots
            int m = t >> 2;                 // 0..127
            int kv = (t & 3) * 4;           // 0,4,8,12
            int gm = mbase + m;
            float4 va = make_float4(0.f, 0.f, 0.f, 0.f);
            float4 vx = va;
            if (gm < NN) {
                va = *(const float4*)&g_agg[(size_t)gm * HD + kb + kv];
                vx = *(const float4*)&Ax  [(size_t)gm * HD + kb + kv];
            }
            *(float4*)&Aa_s[m * 20 + kv] = va;
            *(float4*)&Ax_s[m * 20 + kv] = vx;
        }
        // --- load W tiles (already transposed: row k, col j) ---
#pragma unroll
        for (int p = 0; p < 2; p++) {
            int t = tid + p * 256;          // 0..511 float4 slots
            int k = t >> 5;                 // 0..15
            int j4 = (t & 31) * 4;          // 0..124
            *(float4*)&Wl_s[k * 128 + j4] = *(const float4*)&WlT[(size_t)(kb + k) * HD + jb + j4];
            *(float4*)&Wr_s[k * 128 + j4] = *(const float4*)&WrT[(size_t)(kb + k) * HD + jb + j4];
        }
        __syncthreads();

#pragma unroll
        for (int kk = 0; kk < 16; kk++) {
            float a0[8], a1[8];
#pragma unroll
            for (int i = 0; i < 4; i++) {
                a0[i]     = Aa_s[(ty * 4 + i) * 20 + kk];
                a0[i + 4] = Aa_s[(64 + ty * 4 + i) * 20 + kk];
                a1[i]     = Ax_s[(ty * 4 + i) * 20 + kk];
                a1[i + 4] = Ax_s[(64 + ty * 4 + i) * 20 + kk];
            }
            float4 l0 = *(const float4*)&Wl_s[kk * 128 + tx * 4];
            float4 l1 = *(const float4*)&Wl_s[kk * 128 + 64 + tx * 4];
            float4 r0 = *(const float4*)&Wr_s[kk * 128 + tx * 4];
            float4 r1 = *(const float4*)&Wr_s[kk * 128 + 64 + tx * 4];
            float bl[8] = {l0.x, l0.y, l0.z, l0.w, l1.x, l1.y, l1.z, l1.w};
            float br[8] = {r0.x, r0.y, r0.z, r0.w, r1.x, r1.y, r1.z, r1.w};
#pragma unroll
            for (int i = 0; i < 8; i++)
#pragma unroll
                for (int j = 0; j < 8; j++)
                    acc[i][j] += a0[i] * bl[j] + a1[i] * br[j];
        }
        __syncthreads();
    }

    // --- epilogue: bias + ELU + store ---
    float bv[8];
#pragma unroll
    for (int j = 0; j < 4; j++) {
        bv[j]     = bias[jb + tx * 4 + j];
        bv[j + 4] = bias[jb + 64 + tx * 4 + j];
    }
#pragma unroll
    for (int i = 0; i < 8; i++) {
        int ml = (i < 4) ? (ty * 4 + i) : (64 + ty * 4 + (i - 4));
        int gm = mbase + ml;
        if (gm >= NN) continue;
        float ov[8];
#pragma unroll
        for (int j = 0; j < 8; j++) ov[j] = elu1(acc[i][j] + bv[j]);
        *(float4*)&out[(size_t)gm * HD + jb + tx * 4]      = make_float4(ov[0], ov[1], ov[2], ov[3]);
        *(float4*)&out[(size_t)gm * HD + jb + 64 + tx * 4] = make_float4(ov[4], ov[5], ov[6], ov[7]);
    }
}

// ---------------- launch ----------------
extern "C" void kernel_launch(void* const* d_in, const int* in_sizes, int n_in,
                              void* d_out, int out_size)
{
    const float* x   = (const float*)d_in[0];
    const void*  ei  = d_in[1];                    // int32 or int64 — sniffed on device
    const float* W[6] = {
        (const float*)d_in[2], (const float*)d_in[3],   // Wl1, Wr1
        (const float*)d_in[4], (const float*)d_in[5],   // Wl2, Wr2
        (const float*)d_in[6], (const float*)d_in[7]    // Wl3, Wr3
    };
    const float* bl1 = (const float*)d_in[8];
    const float* bl2 = (const float*)d_in[9];
    const float* bl3 = (const float*)d_in[10];
    float* out = (float*)d_out;

    // dtype sniff + CSR build (once; reused by all 3 layers) + weight transposes
    k_sniff<<<1, 1>>>(ei);
    k_zero_counts<<<(NN + 255) / 256, 256>>>();
    for (int i = 0; i < 6; i++)
        k_transpose<<<(HD * HD + 255) / 256, 256>>>(W[i], i);
    k_hist<<<(NE + 255) / 256, 256>>>(ei);
    k_scan<<<1, 1024>>>();
    k_scatter<<<(NE + 255) / 256, 256>>>(ei);

    dim3 ggrid((NN + 127) / 128, 2);
    const int agrid = (NN * 32 + 255) / 256;

    // layer 1: x -> h1
    k_aggregate<<<agrid, 256>>>(x, 0);
    k_gemm_elu<<<ggrid, 256>>>(x, 0, 0, bl1, nullptr, 1);
    // layer 2: h1 -> h2
    k_aggregate<<<agrid, 256>>>(nullptr, 1);
    k_gemm_elu<<<ggrid, 256>>>(nullptr, 1, 2, bl2, nullptr, 2);
    // layer 3: h2 -> out
    k_aggregate<<<agrid, 256>>>(nullptr, 2);
    k_gemm_elu<<<ggrid, 256>>>(nullptr, 2, 4, bl3, out, 0);
}

// round 12
// speedup vs baseline: 3.1907x; 3.1907x over previous
#include <cuda_runtime.h>
#include <cuda_bf16.h>
#include <math.h>

#define NN 50000
#define NNPAD 50048            // 391 * 128
#define NE 800000
#define HD 256
#define KA 1024                // A row: [agg_h(256)|x_h(256)|agg_l(256)|x_l(256)]
#define KB 1536                // B row: [Wl_h|Wr_h|Wl_l|Wr_l|Wl_h|Wr_h]
#define MTILES (NNPAD / 128)   // 391
#define NCHUNK 24              // 1536 / 64

// ---------------- device scratch ----------------
__device__ __align__(16) float g_h1[NN * HD];
__device__ __align__(16) float g_h2[NN * HD];
__device__ __align__(16) __nv_bfloat16 g_A0[(size_t)NNPAD * KA];
__device__ __align__(16) __nv_bfloat16 g_A1[(size_t)NNPAD * KA];
__device__ __align__(16) __nv_bfloat16 g_Bw[3][256 * KB];
__device__ int g_count[NN];
__device__ int g_fill[NN];
__device__ int g_rowptr[NN + 1];
__device__ int g_col[NE];
__device__ int g_is64;

// ---------------- helpers ----------------
__device__ __forceinline__ unsigned smem_u32(const void* p) {
    unsigned a;
    asm("{ .reg .u64 t; cvta.to.shared.u64 t, %1; cvt.u32.u64 %0, t; }" : "=r"(a) : "l"(p));
    return a;
}
#define CP_ASYNC16(saddr, gptr) \
    asm volatile("cp.async.cg.shared.global [%0], [%1], 16;" :: "r"(saddr), "l"(gptr))
#define CP_COMMIT() asm volatile("cp.async.commit_group;" ::: "memory")
#define CP_WAIT0()  asm volatile("cp.async.wait_group 0;" ::: "memory")

__device__ __forceinline__ float elu1(float v) { return (v > 0.0f) ? v : expm1f(v); }
__device__ __forceinline__ void acc4(float4& a, const float4 b) {
    a.x += b.x; a.y += b.y; a.z += b.z; a.w += b.w;
}
__device__ __forceinline__ void split_f4(float4 v, uint2& hi, uint2& lo) {
    __nv_bfloat162 hxy = __floats2bfloat162_rn(v.x, v.y);
    __nv_bfloat162 hzw = __floats2bfloat162_rn(v.z, v.w);
    float rx = v.x - __low2float(hxy), ry = v.y - __high2float(hxy);
    float rz = v.z - __low2float(hzw), rw = v.w - __high2float(hzw);
    __nv_bfloat162 lxy = __floats2bfloat162_rn(rx, ry);
    __nv_bfloat162 lzw = __floats2bfloat162_rn(rz, rw);
    hi.x = *(unsigned*)&hxy; hi.y = *(unsigned*)&hzw;
    lo.x = *(unsigned*)&lxy; lo.y = *(unsigned*)&lzw;
}
__device__ __forceinline__ int edge_at(const void* ei, int idx, int is64) {
    if (is64) return (int)((const long long*)ei)[idx];
    return ((const int*)ei)[idx];
}

// ---------------- dtype sniff + CSR ----------------
__global__ void k_sniff(const void* ei) {
    const int* w = (const int*)ei;
    int odd_nonzero = 0;
    for (int i = 1; i < 256; i += 2) odd_nonzero |= (w[i] != 0);
    g_is64 = odd_nonzero ? 0 : 1;
}
__global__ void k_zero_counts() {
    int i = blockIdx.x * blockDim.x + threadIdx.x;
    if (i < NN) { g_count[i] = 0; g_fill[i] = 0; }
}
__global__ void k_hist(const void* __restrict__ ei) {
    int e = blockIdx.x * blockDim.x + threadIdx.x;
    if (e < NE) {
        int dst = edge_at(ei, NE + e, g_is64);
        if ((unsigned)dst < NN) atomicAdd(&g_count[dst], 1);
    }
}
__global__ void k_scan() {
    __shared__ int s[1024];
    int tid = threadIdx.x;
    const int chunk = (NN + 1023) / 1024;
    int start = tid * chunk, end = min(start + chunk, NN);
    int sum = 0;
    for (int i = start; i < end; i++) sum += g_count[i];
    s[tid] = sum;
    __syncthreads();
    for (int off = 1; off < 1024; off <<= 1) {
        int v = 0;
        if (tid >= off) v = s[tid - off];
        __syncthreads();
        if (tid >= off) s[tid] += v;
        __syncthreads();
    }
    int run = (tid > 0) ? s[tid - 1] : 0;
    for (int i = start; i < end; i++) { g_rowptr[i] = run; run += g_count[i]; }
    if (tid == 0) g_rowptr[NN] = NE;
}
__global__ void k_scatter(const void* __restrict__ ei) {
    int e = blockIdx.x * blockDim.x + threadIdx.x;
    if (e < NE) {
        int is64 = g_is64;
        int dst = edge_at(ei, NE + e, is64);
        int src = edge_at(ei, e, is64);
        if ((unsigned)dst < NN && (unsigned)src < NN) {
            int pos = g_rowptr[dst] + atomicAdd(&g_fill[dst], 1);
            g_col[pos] = src;
        }
    }
}

// ---------------- weight prep: B[j] = [Wl_h|Wr_h|Wl_l|Wr_l|Wl_h|Wr_h] ----------------
__global__ void k_bprep(const float* __restrict__ Wl, const float* __restrict__ Wr, int layer) {
    int t = blockIdx.x * blockDim.x + threadIdx.x;
    if (t >= 256 * 256) return;
    int j = t >> 8, k = t & 255;
    float wl = Wl[t], wr = Wr[t];
    __nv_bfloat16 hl = __float2bfloat16_rn(wl);
    __nv_bfloat16 hr = __float2bfloat16_rn(wr);
    __nv_bfloat16 ll = __float2bfloat16_rn(wl - __bfloat162float(hl));
    __nv_bfloat16 lr = __float2bfloat16_rn(wr - __bfloat162float(hr));
    __nv_bfloat16* B = &g_Bw[layer][(size_t)j * KB];
    B[k] = hl; B[256 + k] = hr; B[512 + k] = ll;
    B[768 + k] = lr; B[1024 + k] = hl; B[1280 + k] = hr;
}

// ---------------- x prep: fill x_h / x_l segments ----------------
__global__ void k_xprep(const float* __restrict__ x, __nv_bfloat16* __restrict__ A) {
    int t = blockIdx.x * blockDim.x + threadIdx.x;
    if (t >= NN * 64) return;
    int row = t >> 6, g = t & 63;
    float4 v = ((const float4*)(x + (size_t)row * HD))[g];
    uint2 hi, lo;
    split_f4(v, hi, lo);
    __nv_bfloat16* Ar = A + (size_t)row * KA;
    *(uint2*)&Ar[256 + g * 4] = hi;
    *(uint2*)&Ar[768 + g * 4] = lo;
}

// ---------------- aggregation: mean -> agg_h/agg_l segments ----------------
__global__ void k_aggregate(const float* __restrict__ xin, __nv_bfloat16* __restrict__ Aout) {
    int gw = (blockIdx.x * blockDim.x + threadIdx.x) >> 5;
    int lane = threadIdx.x & 31;
    if (gw >= NN) return;

    int beg = g_rowptr[gw], end = g_rowptr[gw + 1];
    float4 a0 = make_float4(0.f, 0.f, 0.f, 0.f);
    float4 a1 = make_float4(0.f, 0.f, 0.f, 0.f);

    int i = beg;
    for (; i + 1 < end; i += 2) {
        int n0 = g_col[i], n1 = g_col[i + 1];
        const float4* r0 = (const float4*)(xin + (size_t)n0 * HD);
        const float4* r1 = (const float4*)(xin + (size_t)n1 * HD);
        float4 v0 = r0[lane], v1 = r0[lane + 32];
        float4 w0 = r1[lane], w1 = r1[lane + 32];
        acc4(a0, v0); acc4(a0, w0);
        acc4(a1, v1); acc4(a1, w1);
    }
    if (i < end) {
        const float4* r0 = (const float4*)(xin + (size_t)g_col[i] * HD);
        acc4(a0, r0[lane]); acc4(a1, r0[lane + 32]);
    }
    float inv = 1.0f / fmaxf((float)(end - beg), 1.0f);
    a0.x *= inv; a0.y *= inv; a0.z *= inv; a0.w *= inv;
    a1.x *= inv; a1.y *= inv; a1.z *= inv; a1.w *= inv;

    uint2 h0, l0, h1, l1;
    split_f4(a0, h0, l0);
    split_f4(a1, h1, l1);
    __nv_bfloat16* Ar = Aout + (size_t)gw * KA;
    *(uint2*)&Ar[lane * 4]       = h0;
    *(uint2*)&Ar[128 + lane * 4] = h1;
    *(uint2*)&Ar[512 + lane * 4] = l0;
    *(uint2*)&Ar[640 + lane * 4] = l1;
}

// ---------------- mma.sync fused dual-GEMM + bias + ELU + next-layer split ----------------
// Block tile 128x128; 8 warps as 2(M) x 4(N); warp tile 64x32 = 4x4 m16n8k16 tiles.
// SMEM: 2 stages x (A 128x64 bf16 pad-72  +  B 128x64 bf16 pad-72) = 73728 B.
#define RS 144                 // padded row stride in bytes (72 bf16)
#define STAGE (128 * RS * 2)   // 36864 B per stage (A + B)
#define SMEM_SZ (2 * STAGE)    // 73728

// chunk c -> A column offset (3-term hi/lo split pairing)
__device__ __forceinline__ int aoff_of(int c) {
    return (c < 16) ? ((c & 7) * 64) : (512 + (c - 16) * 64);
}

// issue cp.async for chunk c into stage s
__device__ __forceinline__ void load_chunk(
    unsigned sb, int s, int c, int mtile, int jb, int lr, int ls,
    const __nv_bfloat16* __restrict__ Abuf, const __nv_bfloat16* __restrict__ Bbuf)
{
    unsigned sA = sb + s * STAGE;
    unsigned sB = sA + 128 * RS;
    int aoff = aoff_of(c);
    int boff = c * 64;
    const __nv_bfloat16* gA = Abuf + (size_t)(mtile + lr) * KA + aoff + ls * 8;
    const __nv_bfloat16* gB = Bbuf + (size_t)(jb + lr) * KB + boff + ls * 8;
    unsigned dA = sA + lr * RS + ls * 16;
    unsigned dB = sB + lr * RS + ls * 16;
#pragma unroll
    for (int p = 0; p < 4; p++) {
        CP_ASYNC16(dA + p * 16, gA + p * 8);
        CP_ASYNC16(dB + p * 16, gB + p * 8);
    }
}

__global__ void __launch_bounds__(256, 2)
k_gemm_mma(const __nv_bfloat16* __restrict__ Abuf,
           const __nv_bfloat16* __restrict__ Bbuf,
           const float* __restrict__ bias,
           float* __restrict__ outF,
           __nv_bfloat16* __restrict__ nextA)
{
    extern __shared__ char smem[];
    unsigned sb = smem_u32(smem);
    int tid = threadIdx.x, lane = tid & 31, wid = tid >> 5;
    int mtile = blockIdx.x * 128;
    int jb = blockIdx.y * 128;

    int wm = (wid & 1) * 64;        // warp M offset
    int wn = (wid >> 1) * 32;       // warp N offset

    // cp.async load slots: each thread covers 4 A + 4 B 16B segments per chunk
    int lr = tid >> 1;              // 0..127 row
    int ls = (tid & 1) * 4;         // segment base 0 or 4 (each seg = 8 bf16 = 16 B)

    float acc[4][4][4];
#pragma unroll
    for (int a = 0; a < 4; a++)
#pragma unroll
        for (int b = 0; b < 4; b++)
#pragma unroll
            for (int d = 0; d < 4; d++) acc[a][b][d] = 0.0f;

    load_chunk(sb, 0, 0, mtile, jb, lr, ls, Abuf, Bbuf);
    CP_COMMIT();
    CP_WAIT0();
    __syncthreads();

    // ldmatrix lane-address bases (within a stage)
    unsigned aLB = ((lane & 7) + ((lane >> 3) & 1) * 8) * RS + (lane >> 4) * 16;
    unsigned bLB = (lane & 7) * RS + ((lane >> 3) & 1) * 16;

    for (int c = 0; c < NCHUNK; c++) {
        int s = c & 1;
        if (c + 1 < NCHUNK) {
            load_chunk(sb, s ^ 1, c + 1, mtile, jb, lr, ls, Abuf, Bbuf);
            CP_COMMIT();
        }

        unsigned sA = sb + s * STAGE;
        unsigned sB = sA + 128 * RS;

#pragma unroll
        for (int ks = 0; ks < 4; ks++) {
            int k0b = ks * 32;             // k offset in bytes (16 bf16)
            unsigned af[4][4];
            unsigned bf[4][2];
#pragma unroll
            for (int mt = 0; mt < 4; mt++) {
                unsigned ad = sA + aLB + (wm + mt * 16) * RS + k0b;
                asm volatile("ldmatrix.sync.aligned.m8n8.x4.shared.b16 {%0,%1,%2,%3}, [%4];"
                    : "=r"(af[mt][0]), "=r"(af[mt][1]), "=r"(af[mt][2]), "=r"(af[mt][3])
                    : "r"(ad));
            }
#pragma unroll
            for (int nt = 0; nt < 4; nt++) {
                unsigned bd = sB + bLB + (wn + nt * 8) * RS + k0b;
                asm volatile("ldmatrix.sync.aligned.m8n8.x2.shared.b16 {%0,%1}, [%2];"
                    : "=r"(bf[nt][0]), "=r"(bf[nt][1]) : "r"(bd));
            }
#pragma unroll
            for (int mt = 0; mt < 4; mt++)
#pragma unroll
                for (int nt = 0; nt < 4; nt++) {
                    asm volatile(
                        "mma.sync.aligned.m16n8k16.row.col.f32.bf16.bf16.f32 "
                        "{%0,%1,%2,%3}, {%4,%5,%6,%7}, {%8,%9}, {%0,%1,%2,%3};"
                        : "+f"(acc[mt][nt][0]), "+f"(acc[mt][nt][1]),
                          "+f"(acc[mt][nt][2]), "+f"(acc[mt][nt][3])
                        : "r"(af[mt][0]), "r"(af[mt][1]), "r"(af[mt][2]), "r"(af[mt][3]),
                          "r"(bf[nt][0]), "r"(bf[nt][1]));
                }
        }
        CP_WAIT0();
        __syncthreads();
    }

    // ---- epilogue: bias + ELU, fp32 out + bf16 hi/lo into next layer's A ----
#pragma unroll
    for (int nt = 0; nt < 4; nt++) {
        int gc = jb + wn + nt * 8 + (lane & 3) * 2;
        float b0 = bias[gc], b1 = bias[gc + 1];
#pragma unroll
        for (int mt = 0; mt < 4; mt++) {
#pragma unroll
            for (int half = 0; half < 2; half++) {
                int gr = mtile + wm + mt * 16 + (lane >> 2) + half * 8;
                if (gr >= NN) continue;
                float e0 = elu1(acc[mt][nt][half * 2]     + b0);
                float e1 = elu1(acc[mt][nt][half * 2 + 1] + b1);
                *(float2*)&outF[(size_t)gr * HD + gc] = make_float2(e0, e1);
                if (nextA) {
                    __nv_bfloat162 hp = __floats2bfloat162_rn(e0, e1);
                    float r0 = e0 - __low2float(hp), r1 = e1 - __high2float(hp);
                    __nv_bfloat162 lp = __floats2bfloat162_rn(r0, r1);
                    __nv_bfloat16* Ar = nextA + (size_t)gr * KA;
                    *(unsigned*)&Ar[256 + gc] = *(unsigned*)&hp;
                    *(unsigned*)&Ar[768 + gc] = *(unsigned*)&lp;
                }
            }
        }
    }
}

// ---------------- launch ----------------
extern "C" void kernel_launch(void* const* d_in, const int* in_sizes, int n_in,
                              void* d_out, int out_size)
{
    const float* x  = (const float*)d_in[0];
    const void*  ei = d_in[1];
    const float* W[6] = {
        (const float*)d_in[2], (const float*)d_in[3],
        (const float*)d_in[4], (const float*)d_in[5],
        (const float*)d_in[6], (const float*)d_in[7]
    };
    const float* bl1 = (const float*)d_in[8];
    const float* bl2 = (const float*)d_in[9];
    const float* bl3 = (const float*)d_in[10];
    float* out = (float*)d_out;

    void *pA0, *pA1, *pB, *ph1, *ph2;
    cudaGetSymbolAddress(&pA0, g_A0);
    cudaGetSymbolAddress(&pA1, g_A1);
    cudaGetSymbolAddress(&pB,  g_Bw);
    cudaGetSymbolAddress(&ph1, g_h1);
    cudaGetSymbolAddress(&ph2, g_h2);
    __nv_bfloat16* A0 = (__nv_bfloat16*)pA0;
    __nv_bfloat16* A1 = (__nv_bfloat16*)pA1;
    __nv_bfloat16* B  = (__nv_bfloat16*)pB;
    float* h1 = (float*)ph1;
    float* h2 = (float*)ph2;

    cudaFuncSetAttribute(k_gemm_mma, cudaFuncAttributeMaxDynamicSharedMemorySize, SMEM_SZ);

    k_sniff<<<1, 1>>>(ei);
    k_zero_counts<<<(NN + 255) / 256, 256>>>();
    for (int l = 0; l < 3; l++)
        k_bprep<<<(256 * 256 + 255) / 256, 256>>>(W[2 * l], W[2 * l + 1], l);
    k_hist<<<(NE + 255) / 256, 256>>>(ei);
    k_scan<<<1, 1024>>>();
    k_scatter<<<(NE + 255) / 256, 256>>>(ei);
    k_xprep<<<(NN * 64 + 255) / 256, 256>>>(x, A0);

    const int agrid = (NN * 32 + 255) / 256;
    dim3 ggrid(MTILES, 2);

    k_aggregate<<<agrid, 256>>>(x, A0);
    k_gemm_mma<<<ggrid, 256, SMEM_SZ>>>(A0, B + 0 * 256 * KB, bl1, h1, A1);
    k_aggregate<<<agrid, 256>>>(h1, A1);
    k_gemm_mma<<<ggrid, 256, SMEM_SZ>>>(A1, B + 1 * 256 * KB, bl2, h2, A0);
    k_aggregate<<<agrid, 256>>>(h2, A0);
    k_gemm_mma<<<ggrid, 256, SMEM_SZ>>>(A0, B + 2 * 256 * KB, bl3, out, nullptr);
}

// round 14
// speedup vs baseline: 3.2401x; 1.0155x over previous
#include <cuda_runtime.h>
#include <cuda_bf16.h>
#include <math.h>

#define NN 50000
#define NNPAD 50048            // 391 * 128
#define NE 800000
#define HD 256
#define KA 1024                // A row: [agg_h(256)|x_h(256)|agg_l(256)|x_l(256)]
#define KB 1536                // B row: [Wl_h|Wr_h|Wl_l|Wr_l|Wl_h|Wr_h]
#define MTILES (NNPAD / 128)   // 391
#define NCHUNK 24              // 1536 / 64

// ---------------- device scratch ----------------
__device__ __align__(16) float g_h1[NN * HD];
__device__ __align__(16) float g_h2[NN * HD];
__device__ __align__(16) __nv_bfloat16 g_A0[(size_t)NNPAD * KA];
__device__ __align__(16) __nv_bfloat16 g_A1[(size_t)NNPAD * KA];
__device__ __align__(16) __nv_bfloat16 g_Bw[3][256 * KB];
__device__ int g_count[NN];
__device__ int g_fill[NN];
__device__ int g_rowptr[NN + 1];
__device__ int g_col[NE];
__device__ int g_is64;

// ---------------- helpers ----------------
__device__ __forceinline__ unsigned smem_u32(const void* p) {
    unsigned a;
    asm("{ .reg .u64 t; cvta.to.shared.u64 t, %1; cvt.u32.u64 %0, t; }" : "=r"(a) : "l"(p));
    return a;
}
#define CP_ASYNC16(saddr, gptr) \
    asm volatile("cp.async.cg.shared.global [%0], [%1], 16;" :: "r"(saddr), "l"(gptr))
#define CP_COMMIT() asm volatile("cp.async.commit_group;" ::: "memory")
#define CP_WAIT0()  asm volatile("cp.async.wait_group 0;" ::: "memory")

__device__ __forceinline__ float elu1(float v) { return (v > 0.0f) ? v : expm1f(v); }
__device__ __forceinline__ void acc4(float4& a, const float4 b) {
    a.x += b.x; a.y += b.y; a.z += b.z; a.w += b.w;
}
__device__ __forceinline__ void split_f4(float4 v, uint2& hi, uint2& lo) {
    __nv_bfloat162 hxy = __floats2bfloat162_rn(v.x, v.y);
    __nv_bfloat162 hzw = __floats2bfloat162_rn(v.z, v.w);
    float rx = v.x - __low2float(hxy), ry = v.y - __high2float(hxy);
    float rz = v.z - __low2float(hzw), rw = v.w - __high2float(hzw);
    __nv_bfloat162 lxy = __floats2bfloat162_rn(rx, ry);
    __nv_bfloat162 lzw = __floats2bfloat162_rn(rz, rw);
    hi.x = *(unsigned*)&hxy; hi.y = *(unsigned*)&hzw;
    lo.x = *(unsigned*)&lxy; lo.y = *(unsigned*)&lzw;
}
__device__ __forceinline__ int edge_at(const void* ei, int idx, int is64) {
    if (is64) return (int)((const long long*)ei)[idx];
    return ((const int*)ei)[idx];
}

// ---------------- dtype sniff + CSR ----------------
__global__ void k_sniff(const void* ei) {
    const int* w = (const int*)ei;
    int odd_nonzero = 0;
    for (int i = 1; i < 256; i += 2) odd_nonzero |= (w[i] != 0);
    g_is64 = odd_nonzero ? 0 : 1;
}
__global__ void k_zero_counts() {
    int i = blockIdx.x * blockDim.x + threadIdx.x;
    if (i < NN) { g_count[i] = 0; g_fill[i] = 0; }
}
__global__ void k_hist(const void* __restrict__ ei) {
    int e = blockIdx.x * blockDim.x + threadIdx.x;
    if (e < NE) {
        int dst = edge_at(ei, NE + e, g_is64);
        if ((unsigned)dst < NN) atomicAdd(&g_count[dst], 1);
    }
}
__global__ void k_scan() {
    __shared__ int s[1024];
    int tid = threadIdx.x;
    const int chunk = (NN + 1023) / 1024;
    int start = tid * chunk, end = min(start + chunk, NN);
    int sum = 0;
    for (int i = start; i < end; i++) sum += g_count[i];
    s[tid] = sum;
    __syncthreads();
    for (int off = 1; off < 1024; off <<= 1) {
        int v = 0;
        if (tid >= off) v = s[tid - off];
        __syncthreads();
        if (tid >= off) s[tid] += v;
        __syncthreads();
    }
    int run = (tid > 0) ? s[tid - 1] : 0;
    for (int i = start; i < end; i++) { g_rowptr[i] = run; run += g_count[i]; }
    if (tid == 0) g_rowptr[NN] = NE;
}
__global__ void k_scatter(const void* __restrict__ ei) {
    int e = blockIdx.x * blockDim.x + threadIdx.x;
    if (e < NE) {
        int is64 = g_is64;
        int dst = edge_at(ei, NE + e, is64);
        int src = edge_at(ei, e, is64);
        if ((unsigned)dst < NN && (unsigned)src < NN) {
            int pos = g_rowptr[dst] + atomicAdd(&g_fill[dst], 1);
            g_col[pos] = src;
        }
    }
}

// ---------------- weight prep: B[j] = [Wl_h|Wr_h|Wl_l|Wr_l|Wl_h|Wr_h] ----------------
__global__ void k_bprep(const float* __restrict__ Wl, const float* __restrict__ Wr, int layer) {
    int t = blockIdx.x * blockDim.x + threadIdx.x;
    if (t >= 256 * 256) return;
    int j = t >> 8, k = t & 255;
    float wl = Wl[t], wr = Wr[t];
    __nv_bfloat16 hl = __float2bfloat16_rn(wl);
    __nv_bfloat16 hr = __float2bfloat16_rn(wr);
    __nv_bfloat16 ll = __float2bfloat16_rn(wl - __bfloat162float(hl));
    __nv_bfloat16 lr = __float2bfloat16_rn(wr - __bfloat162float(hr));
    __nv_bfloat16* B = &g_Bw[layer][(size_t)j * KB];
    B[k] = hl; B[256 + k] = hr; B[512 + k] = ll;
    B[768 + k] = lr; B[1024 + k] = hl; B[1280 + k] = hr;
}

// ---------------- x prep: fill x_h / x_l segments ----------------
__global__ void k_xprep(const float* __restrict__ x, __nv_bfloat16* __restrict__ A) {
    int t = blockIdx.x * blockDim.x + threadIdx.x;
    if (t >= NN * 64) return;
    int row = t >> 6, g = t & 63;
    float4 v = ((const float4*)(x + (size_t)row * HD))[g];
    uint2 hi, lo;
    split_f4(v, hi, lo);
    __nv_bfloat16* Ar = A + (size_t)row * KA;
    *(uint2*)&Ar[256 + g * 4] = hi;
    *(uint2*)&Ar[768 + g * 4] = lo;
}

// ---------------- aggregation: mean -> agg_h/agg_l segments (unroll 4) ----------------
__global__ void k_aggregate(const float* __restrict__ xin, __nv_bfloat16* __restrict__ Aout) {
    int gw = (blockIdx.x * blockDim.x + threadIdx.x) >> 5;
    int lane = threadIdx.x & 31;
    if (gw >= NN) return;

    int beg = g_rowptr[gw], end = g_rowptr[gw + 1];
    float4 a0 = make_float4(0.f, 0.f, 0.f, 0.f);
    float4 a1 = make_float4(0.f, 0.f, 0.f, 0.f);

    int i = beg;
    for (; i + 3 < end; i += 4) {           // 8 independent LDG.128 in flight
        int n0 = g_col[i],     n1 = g_col[i + 1];
        int n2 = g_col[i + 2], n3 = g_col[i + 3];
        const float4* r0 = (const float4*)(xin + (size_t)n0 * HD);
        const float4* r1 = (const float4*)(xin + (size_t)n1 * HD);
        const float4* r2 = (const float4*)(xin + (size_t)n2 * HD);
        const float4* r3 = (const float4*)(xin + (size_t)n3 * HD);
        float4 v0 = r0[lane],      v1 = r1[lane];
        float4 v2 = r2[lane],      v3 = r3[lane];
        float4 u0 = r0[lane + 32], u1 = r1[lane + 32];
        float4 u2 = r2[lane + 32], u3 = r3[lane + 32];
        acc4(a0, v0); acc4(a0, v1); acc4(a0, v2); acc4(a0, v3);
        acc4(a1, u0); acc4(a1, u1); acc4(a1, u2); acc4(a1, u3);
    }
    for (; i < end; i++) {
        const float4* r0 = (const float4*)(xin + (size_t)g_col[i] * HD);
        acc4(a0, r0[lane]); acc4(a1, r0[lane + 32]);
    }
    float inv = 1.0f / fmaxf((float)(end - beg), 1.0f);
    a0.x *= inv; a0.y *= inv; a0.z *= inv; a0.w *= inv;
    a1.x *= inv; a1.y *= inv; a1.z *= inv; a1.w *= inv;

    uint2 h0, l0, h1, l1;
    split_f4(a0, h0, l0);
    split_f4(a1, h1, l1);
    __nv_bfloat16* Ar = Aout + (size_t)gw * KA;
    *(uint2*)&Ar[lane * 4]       = h0;
    *(uint2*)&Ar[128 + lane * 4] = h1;
    *(uint2*)&Ar[512 + lane * 4] = l0;
    *(uint2*)&Ar[640 + lane * 4] = l1;
}

// ---------------- mma.sync fused dual-GEMM + bias + ELU + next-layer split ----------------
// Block tile 128x128; 8 warps as 2(M) x 4(N); warp tile 64x32 = 4x4 m16n8k16 tiles.
// Grid (2, MTILES): both jb blocks of an mtile are adjacent in delivery order -> A rows
// stay L2-hot for the second read (A buffer is ~100 MB vs 126 MB L2).
#define RS 144                 // padded row stride in bytes (72 bf16)
#define STAGE (128 * RS * 2)   // 36864 B per stage (A + B)
#define SMEM_SZ (2 * STAGE)    // 73728

// chunk c -> A column offset (3-term hi/lo split pairing)
__device__ __forceinline__ int aoff_of(int c) {
    return (c < 16) ? ((c & 7) * 64) : (512 + (c - 16) * 64);
}

// issue cp.async for chunk c into stage s
__device__ __forceinline__ void load_chunk(
    unsigned sb, int s, int c, int mtile, int jb, int lr, int ls,
    const __nv_bfloat16* __restrict__ Abuf, const __nv_bfloat16* __restrict__ Bbuf)
{
    unsigned sA = sb + s * STAGE;
    unsigned sB = sA + 128 * RS;
    int aoff = aoff_of(c);
    int boff = c * 64;
    const __nv_bfloat16* gA = Abuf + (size_t)(mtile + lr) * KA + aoff + ls * 8;
    const __nv_bfloat16* gB = Bbuf + (size_t)(jb + lr) * KB + boff + ls * 8;
    unsigned dA = sA + lr * RS + ls * 16;
    unsigned dB = sB + lr * RS + ls * 16;
#pragma unroll
    for (int p = 0; p < 4; p++) {
        CP_ASYNC16(dA + p * 16, gA + p * 8);
        CP_ASYNC16(dB + p * 16, gB + p * 8);
    }
}

__global__ void __launch_bounds__(256, 2)
k_gemm_mma(const __nv_bfloat16* __restrict__ Abuf,
           const __nv_bfloat16* __restrict__ Bbuf,
           const float* __restrict__ bias,
           float* __restrict__ outF,
           __nv_bfloat16* __restrict__ nextA)
{
    extern __shared__ char smem[];
    unsigned sb = smem_u32(smem);
    int tid = threadIdx.x, lane = tid & 31, wid = tid >> 5;
    int jb = blockIdx.x * 128;          // fast dim: jb pairs share mtile -> L2 reuse
    int mtile = blockIdx.y * 128;

    int wm = (wid & 1) * 64;        // warp M offset
    int wn = (wid >> 1) * 32;       // warp N offset

    // cp.async load slots: each thread covers 4 A + 4 B 16B segments per chunk
    int lr = tid >> 1;              // 0..127 row
    int ls = (tid & 1) * 4;         // segment base 0 or 4 (each seg = 8 bf16 = 16 B)

    float acc[4][4][4];
#pragma unroll
    for (int a = 0; a < 4; a++)
#pragma unroll
        for (int b = 0; b < 4; b++)
#pragma unroll
            for (int d = 0; d < 4; d++) acc[a][b][d] = 0.0f;

    load_chunk(sb, 0, 0, mtile, jb, lr, ls, Abuf, Bbuf);
    CP_COMMIT();
    CP_WAIT0();
    __syncthreads();

    // ldmatrix lane-address bases (within a stage)
    unsigned aLB = ((lane & 7) + ((lane >> 3) & 1) * 8) * RS + (lane >> 4) * 16;
    unsigned bLB = (lane & 7) * RS + ((lane >> 3) & 1) * 16;

    for (int c = 0; c < NCHUNK; c++) {
        int s = c & 1;
        if (c + 1 < NCHUNK) {
            load_chunk(sb, s ^ 1, c + 1, mtile, jb, lr, ls, Abuf, Bbuf);
            CP_COMMIT();
        }

        unsigned sA = sb + s * STAGE;
        unsigned sB = sA + 128 * RS;

#pragma unroll
        for (int ks = 0; ks < 4; ks++) {
            int k0b = ks * 32;             // k offset in bytes (16 bf16)
            unsigned af[4][4];
            unsigned bf[4][2];
#pragma unroll
            for (int mt = 0; mt < 4; mt++) {
                unsigned ad = sA + aLB + (wm + mt * 16) * RS + k0b;
                asm volatile("ldmatrix.sync.aligned.m8n8.x4.shared.b16 {%0,%1,%2,%3}, [%4];"
                    : "=r"(af[mt][0]), "=r"(af[mt][1]), "=r"(af[mt][2]), "=r"(af[mt][3])
                    : "r"(ad));
            }
#pragma unroll
            for (int nt = 0; nt < 4; nt++) {
                unsigned bd = sB + bLB + (wn + nt * 8) * RS + k0b;
                asm volatile("ldmatrix.sync.aligned.m8n8.x2.shared.b16 {%0,%1}, [%2];"
                    : "=r"(bf[nt][0]), "=r"(bf[nt][1]) : "r"(bd));
            }
#pragma unroll
            for (int mt = 0; mt < 4; mt++)
#pragma unroll
                for (int nt = 0; nt < 4; nt++) {
                    asm volatile(
                        "mma.sync.aligned.m16n8k16.row.col.f32.bf16.bf16.f32 "
                        "{%0,%1,%2,%3}, {%4,%5,%6,%7}, {%8,%9}, {%0,%1,%2,%3};"
                        : "+f"(acc[mt][nt][0]), "+f"(acc[mt][nt][1]),
                          "+f"(acc[mt][nt][2]), "+f"(acc[mt][nt][3])
                        : "r"(af[mt][0]), "r"(af[mt][1]), "r"(af[mt][2]), "r"(af[mt][3]),
                          "r"(bf[nt][0]), "r"(bf[nt][1]));
                }
        }
        CP_WAIT0();
        __syncthreads();
    }

    // ---- epilogue: bias + ELU, fp32 out + bf16 hi/lo into next layer's A ----
#pragma unroll
    for (int nt = 0; nt < 4; nt++) {
        int gc = jb + wn + nt * 8 + (lane & 3) * 2;
        float b0 = bias[gc], b1 = bias[gc + 1];
#pragma unroll
        for (int mt = 0; mt < 4; mt++) {
#pragma unroll
            for (int half = 0; half < 2; half++) {
                int gr = mtile + wm + mt * 16 + (lane >> 2) + half * 8;
                if (gr >= NN) continue;
                float e0 = elu1(acc[mt][nt][half * 2]     + b0);
                float e1 = elu1(acc[mt][nt][half * 2 + 1] + b1);
                *(float2*)&outF[(size_t)gr * HD + gc] = make_float2(e0, e1);
                if (nextA) {
                    __nv_bfloat162 hp = __floats2bfloat162_rn(e0, e1);
                    float r0 = e0 - __low2float(hp), r1 = e1 - __high2float(hp);
                    __nv_bfloat162 lp = __floats2bfloat162_rn(r0, r1);
                    __nv_bfloat16* Ar = nextA + (size_t)gr * KA;
                    *(unsigned*)&Ar[256 + gc] = *(unsigned*)&hp;
                    *(unsigned*)&Ar[768 + gc] = *(unsigned*)&lp;
                }
            }
        }
    }
}

// ---------------- launch ----------------
extern "C" void kernel_launch(void* const* d_in, const int* in_sizes, int n_in,
                              void* d_out, int out_size)
{
    const float* x  = (const float*)d_in[0];
    const void*  ei = d_in[1];
    const float* W[6] = {
        (const float*)d_in[2], (const float*)d_in[3],
        (const float*)d_in[4], (const float*)d_in[5],
        (const float*)d_in[6], (const float*)d_in[7]
    };
    const float* bl1 = (const float*)d_in[8];
    const float* bl2 = (const float*)d_in[9];
    const float* bl3 = (const float*)d_in[10];
    float* out = (float*)d_out;

    void *pA0, *pA1, *pB, *ph1, *ph2;
    cudaGetSymbolAddress(&pA0, g_A0);
    cudaGetSymbolAddress(&pA1, g_A1);
    cudaGetSymbolAddress(&pB,  g_Bw);
    cudaGetSymbolAddress(&ph1, g_h1);
    cudaGetSymbolAddress(&ph2, g_h2);
    __nv_bfloat16* A0 = (__nv_bfloat16*)pA0;
    __nv_bfloat16* A1 = (__nv_bfloat16*)pA1;
    __nv_bfloat16* B  = (__nv_bfloat16*)pB;
    float* h1 = (float*)ph1;
    float* h2 = (float*)ph2;

    cudaFuncSetAttribute(k_gemm_mma, cudaFuncAttributeMaxDynamicSharedMemorySize, SMEM_SZ);

    const int agrid = (NN * 32 + 255) / 256;
    dim3 ggrid(2, MTILES);    // jb fast -> A rows L2-hot across the jb pair

    // launches 0..4: sniff + CSR; launch 5 = first k_aggregate (ncu -s 5 profiles it)
    k_sniff<<<1, 1>>>(ei);
    k_zero_counts<<<(NN + 255) / 256, 256>>>();
    k_hist<<<(NE + 255) / 256, 256>>>(ei);
    k_scan<<<1, 1024>>>();
    k_scatter<<<(NE + 255) / 256, 256>>>(ei);
    k_aggregate<<<agrid, 256>>>(x, A0);                  // launch #5

    for (int l = 0; l < 3; l++)
        k_bprep<<<(256 * 256 + 255) / 256, 256>>>(W[2 * l], W[2 * l + 1], l);
    k_xprep<<<(NN * 64 + 255) / 256, 256>>>(x, A0);

    k_gemm_mma<<<ggrid, 256, SMEM_SZ>>>(A0, B + 0 * 256 * KB, bl1, h1, A1);
    k_aggregate<<<agrid, 256>>>(h1, A1);
    k_gemm_mma<<<ggrid, 256, SMEM_SZ>>>(A1, B + 1 * 256 * KB, bl2, h2, A0);
    k_aggregate<<<agrid, 256>>>(h2, A0);
    k_gemm_mma<<<ggrid, 256, SMEM_SZ>>>(A0, B + 2 * 256 * KB, bl3, out, nullptr);
}

// round 16
// speedup vs baseline: 3.4212x; 1.0559x over previous
#include <cuda_runtime.h>
#include <cuda_bf16.h>
#include <math.h>

#define NN 50000
#define NNPAD 50048            // 391 * 128
#define NE 800000
#define HD 256
#define KA 1024                // A row: [agg_h(256)|x_h(256)|agg_l(256)|x_l(256)]
#define KB 1536                // B row: [Wl_h|Wr_h|Wl_l|Wr_l|Wl_h|Wr_h]
#define MTILES (NNPAD / 128)   // 391
#define NCHUNK 24              // 1536 / 64
#define NBLK 196               // ceil(NN / 256) scan blocks

// ---------------- device scratch ----------------
__device__ __align__(16) float g_h1[NN * HD];
__device__ __align__(16) float g_h2[NN * HD];
__device__ __align__(16) __nv_bfloat16 g_A0[(size_t)NNPAD * KA];
__device__ __align__(16) __nv_bfloat16 g_A1[(size_t)NNPAD * KA];
__device__ __align__(16) __nv_bfloat16 g_Bw[3][256 * KB];
__device__ int g_count[NN];
__device__ int g_fill[NN];
__device__ int g_rowptr[NN + 1];
__device__ int g_col[NE];
__device__ int g_bsum[NBLK];
__device__ int g_boff[NBLK];
__device__ int g_is64;

// ---------------- helpers ----------------
__device__ __forceinline__ unsigned smem_u32(const void* p) {
    unsigned a;
    asm("{ .reg .u64 t; cvta.to.shared.u64 t, %1; cvt.u32.u64 %0, t; }" : "=r"(a) : "l"(p));
    return a;
}
#define CP_ASYNC16(saddr, gptr) \
    asm volatile("cp.async.cg.shared.global [%0], [%1], 16;" :: "r"(saddr), "l"(gptr))
#define CP_COMMIT() asm volatile("cp.async.commit_group;" ::: "memory")
#define CP_WAIT0()  asm volatile("cp.async.wait_group 0;" ::: "memory")

__device__ __forceinline__ float elu1(float v) { return (v > 0.0f) ? v : expm1f(v); }
__device__ __forceinline__ void acc4(float4& a, const float4 b) {
    a.x += b.x; a.y += b.y; a.z += b.z; a.w += b.w;
}
__device__ __forceinline__ void split_f4(float4 v, uint2& hi, uint2& lo) {
    __nv_bfloat162 hxy = __floats2bfloat162_rn(v.x, v.y);
    __nv_bfloat162 hzw = __floats2bfloat162_rn(v.z, v.w);
    float rx = v.x - __low2float(hxy), ry = v.y - __high2float(hxy);
    float rz = v.z - __low2float(hzw), rw = v.w - __high2float(hzw);
    __nv_bfloat162 lxy = __floats2bfloat162_rn(rx, ry);
    __nv_bfloat162 lzw = __floats2bfloat162_rn(rz, rw);
    hi.x = *(unsigned*)&hxy; hi.y = *(unsigned*)&hzw;
    lo.x = *(unsigned*)&lxy; lo.y = *(unsigned*)&lzw;
}
__device__ __forceinline__ int edge_at(const void* ei, int idx, int is64) {
    if (is64) return (int)((const long long*)ei)[idx];
    return ((const int*)ei)[idx];
}

// block-wide inclusive scan of v over 256 threads; returns inclusive sum, total via *tot
__device__ __forceinline__ int block_iscan256(int v, int* tot, int* ws) {
    int lane = threadIdx.x & 31, w = threadIdx.x >> 5;
    int s = v;
#pragma unroll
    for (int o = 1; o < 32; o <<= 1) {
        int t = __shfl_up_sync(0xffffffffu, s, o);
        if (lane >= o) s += t;
    }
    if (lane == 31) ws[w] = s;
    __syncthreads();
    if (w == 0) {
        int t = (lane < 8) ? ws[lane] : 0;
#pragma unroll
        for (int o = 1; o < 8; o <<= 1) {
            int u = __shfl_up_sync(0xffffffffu, t, o);
            if (lane >= o) t += u;
        }
        if (lane < 8) ws[lane] = t;
    }
    __syncthreads();
    int base = (w > 0) ? ws[w - 1] : 0;
    *tot = ws[7];
    return base + s;
}

// ---------------- dtype sniff + CSR ----------------
__global__ void k_sniff(const void* ei) {
    const int* w = (const int*)ei;
    int odd_nonzero = 0;
    for (int i = 1; i < 256; i += 2) odd_nonzero |= (w[i] != 0);
    g_is64 = odd_nonzero ? 0 : 1;
}
__global__ void k_zero_counts() {
    int i = blockIdx.x * blockDim.x + threadIdx.x;
    if (i < NN) { g_count[i] = 0; g_fill[i] = 0; }
}
__global__ void k_hist(const void* __restrict__ ei) {
    int e = blockIdx.x * blockDim.x + threadIdx.x;
    if (e < NE) {
        int dst = edge_at(ei, NE + e, g_is64);
        if ((unsigned)dst < NN) atomicAdd(&g_count[dst], 1);
    }
}
// parallel exclusive scan, 3 phases
__global__ void k_scan1() {
    __shared__ int ws[8];
    int i = blockIdx.x * 256 + threadIdx.x;
    int v = (i < NN) ? g_count[i] : 0;
    int tot, inc = block_iscan256(v, &tot, ws);
    if (i < NN) g_rowptr[i] = inc - v;          // local exclusive prefix
    if (threadIdx.x == 0) g_bsum[blockIdx.x] = tot;
}
__global__ void k_scan2() {
    __shared__ int ws[8];
    int i = threadIdx.x;
    int v = (i < NBLK) ? g_bsum[i] : 0;
    int tot, inc = block_iscan256(v, &tot, ws);
    if (i < NBLK) g_boff[i] = inc - v;          // exclusive block offsets
    if (i == 0) g_rowptr[NN] = NE;
}
__global__ void k_scan3() {
    int i = blockIdx.x * 256 + threadIdx.x;
    if (i < NN) g_rowptr[i] += g_boff[blockIdx.x];
}
__global__ void k_scatter(const void* __restrict__ ei) {
    int e = blockIdx.x * blockDim.x + threadIdx.x;
    if (e < NE) {
        int is64 = g_is64;
        int dst = edge_at(ei, NE + e, is64);
        int src = edge_at(ei, e, is64);
        if ((unsigned)dst < NN && (unsigned)src < NN) {
            int pos = g_rowptr[dst] + atomicAdd(&g_fill[dst], 1);
            g_col[pos] = src;
        }
    }
}

// ---------------- weight prep: B[j] = [Wl_h|Wr_h|Wl_l|Wr_l|Wl_h|Wr_h] ----------------
__global__ void k_bprep(const float* __restrict__ Wl, const float* __restrict__ Wr, int layer) {
    int t = blockIdx.x * blockDim.x + threadIdx.x;
    if (t >= 256 * 256) return;
    int j = t >> 8, k = t & 255;
    float wl = Wl[t], wr = Wr[t];
    __nv_bfloat16 hl = __float2bfloat16_rn(wl);
    __nv_bfloat16 hr = __float2bfloat16_rn(wr);
    __nv_bfloat16 ll = __float2bfloat16_rn(wl - __bfloat162float(hl));
    __nv_bfloat16 lr = __float2bfloat16_rn(wr - __bfloat162float(hr));
    __nv_bfloat16* B = &g_Bw[layer][(size_t)j * KB];
    B[k] = hl; B[256 + k] = hr; B[512 + k] = ll;
    B[768 + k] = lr; B[1024 + k] = hl; B[1280 + k] = hr;
}

// ---------------- aggregation: mean -> agg_h/agg_l (+ optional own-row x split) ----------------
__global__ void k_aggregate(const float* __restrict__ xin, __nv_bfloat16* __restrict__ Aout,
                            int withX) {
    int gw = (blockIdx.x * blockDim.x + threadIdx.x) >> 5;
    int lane = threadIdx.x & 31;
    if (gw >= NN) return;

    int beg = g_rowptr[gw], end = g_rowptr[gw + 1];
    float4 a0 = make_float4(0.f, 0.f, 0.f, 0.f);
    float4 a1 = make_float4(0.f, 0.f, 0.f, 0.f);

    int i = beg;
    for (; i + 3 < end; i += 4) {           // 8 independent LDG.128 in flight
        int n0 = g_col[i],     n1 = g_col[i + 1];
        int n2 = g_col[i + 2], n3 = g_col[i + 3];
        const float4* r0 = (const float4*)(xin + (size_t)n0 * HD);
        const float4* r1 = (const float4*)(xin + (size_t)n1 * HD);
        const float4* r2 = (const float4*)(xin + (size_t)n2 * HD);
        const float4* r3 = (const float4*)(xin + (size_t)n3 * HD);
        float4 v0 = r0[lane],      v1 = r1[lane];
        float4 v2 = r2[lane],      v3 = r3[lane];
        float4 u0 = r0[lane + 32], u1 = r1[lane + 32];
        float4 u2 = r2[lane + 32], u3 = r3[lane + 32];
        acc4(a0, v0); acc4(a0, v1); acc4(a0, v2); acc4(a0, v3);
        acc4(a1, u0); acc4(a1, u1); acc4(a1, u2); acc4(a1, u3);
    }
    for (; i < end; i++) {
        const float4* r0 = (const float4*)(xin + (size_t)g_col[i] * HD);
        acc4(a0, r0[lane]); acc4(a1, r0[lane + 32]);
    }
    float inv = 1.0f / fmaxf((float)(end - beg), 1.0f);
    a0.x *= inv; a0.y *= inv; a0.z *= inv; a0.w *= inv;
    a1.x *= inv; a1.y *= inv; a1.z *= inv; a1.w *= inv;

    uint2 h0, l0, h1, l1;
    split_f4(a0, h0, l0);
    split_f4(a1, h1, l1);
    __nv_bfloat16* Ar = Aout + (size_t)gw * KA;
    *(uint2*)&Ar[lane * 4]       = h0;
    *(uint2*)&Ar[128 + lane * 4] = h1;
    *(uint2*)&Ar[512 + lane * 4] = l0;
    *(uint2*)&Ar[640 + lane * 4] = l1;

    if (withX) {   // layer-1 only: split own x row into x_h / x_l segments (replaces k_xprep)
        const float4* rs = (const float4*)(xin + (size_t)gw * HD);
        float4 x0 = rs[lane], x1 = rs[lane + 32];
        uint2 xh0, xl0, xh1, xl1;
        split_f4(x0, xh0, xl0);
        split_f4(x1, xh1, xl1);
        *(uint2*)&Ar[256 + lane * 4] = xh0;
        *(uint2*)&Ar[384 + lane * 4] = xh1;
        *(uint2*)&Ar[768 + lane * 4] = xl0;
        *(uint2*)&Ar[896 + lane * 4] = xl1;
    }
}

// ---------------- mma.sync fused dual-GEMM + bias + ELU + next-layer split ----------------
// Block tile 128x128; 8 warps as 2(M) x 4(N); warp tile 64x32 = 4x4 m16n8k16 tiles.
// Grid (2, MTILES): jb pair of an mtile adjacent in delivery order -> A rows L2-hot.
#define RS 144                 // padded row stride in bytes (72 bf16)
#define STAGE (128 * RS * 2)   // 36864 B per stage (A + B)
#define SMEM_SZ (2 * STAGE)    // 73728

// chunk c -> A column offset (3-term hi/lo split pairing)
__device__ __forceinline__ int aoff_of(int c) {
    return (c < 16) ? ((c & 7) * 64) : (512 + (c - 16) * 64);
}

// issue cp.async for chunk c into stage s
__device__ __forceinline__ void load_chunk(
    unsigned sb, int s, int c, int mtile, int jb, int lr, int ls,
    const __nv_bfloat16* __restrict__ Abuf, const __nv_bfloat16* __restrict__ Bbuf)
{
    unsigned sA = sb + s * STAGE;
    unsigned sB = sA + 128 * RS;
    int aoff = aoff_of(c);
    int boff = c * 64;
    const __nv_bfloat16* gA = Abuf + (size_t)(mtile + lr) * KA + aoff + ls * 8;
    const __nv_bfloat16* gB = Bbuf + (size_t)(jb + lr) * KB + boff + ls * 8;
    unsigned dA = sA + lr * RS + ls * 16;
    unsigned dB = sB + lr * RS + ls * 16;
#pragma unroll
    for (int p = 0; p < 4; p++) {
        CP_ASYNC16(dA + p * 16, gA + p * 8);
        CP_ASYNC16(dB + p * 16, gB + p * 8);
    }
}

__global__ void __launch_bounds__(256, 2)
k_gemm_mma(const __nv_bfloat16* __restrict__ Abuf,
           const __nv_bfloat16* __restrict__ Bbuf,
           const float* __restrict__ bias,
           float* __restrict__ outF,
           __nv_bfloat16* __restrict__ nextA)
{
    extern __shared__ char smem[];
    unsigned sb = smem_u32(smem);
    int tid = threadIdx.x, lane = tid & 31, wid = tid >> 5;
    int jb = blockIdx.x * 128;          // fast dim: jb pairs share mtile -> L2 reuse
    int mtile = blockIdx.y * 128;

    int wm = (wid & 1) * 64;        // warp M offset
    int wn = (wid >> 1) * 32;       // warp N offset

    int lr = tid >> 1;              // 0..127 row
    int ls = (tid & 1) * 4;         // segment base 0 or 4 (each seg = 8 bf16 = 16 B)

    float acc[4][4][4];
#pragma unroll
    for (int a = 0; a < 4; a++)
#pragma unroll
        for (int b = 0; b < 4; b++)
#pragma unroll
            for (int d = 0; d < 4; d++) acc[a][b][d] = 0.0f;

    load_chunk(sb, 0, 0, mtile, jb, lr, ls, Abuf, Bbuf);
    CP_COMMIT();
    CP_WAIT0();
    __syncthreads();

    unsigned aLB = ((lane & 7) + ((lane >> 3) & 1) * 8) * RS + (lane >> 4) * 16;
    unsigned bLB = (lane & 7) * RS + ((lane >> 3) & 1) * 16;

    for (int c = 0; c < NCHUNK; c++) {
        int s = c & 1;
        if (c + 1 < NCHUNK) {
            load_chunk(sb, s ^ 1, c + 1, mtile, jb, lr, ls, Abuf, Bbuf);
            CP_COMMIT();
        }

        unsigned sA = sb + s * STAGE;
        unsigned sB = sA + 128 * RS;

#pragma unroll
        for (int ks = 0; ks < 4; ks++) {
            int k0b = ks * 32;
            unsigned af[4][4];
            unsigned bf[4][2];
#pragma unroll
            for (int mt = 0; mt < 4; mt++) {
                unsigned ad = sA + aLB + (wm + mt * 16) * RS + k0b;
                asm volatile("ldmatrix.sync.aligned.m8n8.x4.shared.b16 {%0,%1,%2,%3}, [%4];"
                    : "=r"(af[mt][0]), "=r"(af[mt][1]), "=r"(af[mt][2]), "=r"(af[mt][3])
                    : "r"(ad));
            }
#pragma unroll
            for (int nt = 0; nt < 4; nt++) {
                unsigned bd = sB + bLB + (wn + nt * 8) * RS + k0b;
                asm volatile("ldmatrix.sync.aligned.m8n8.x2.shared.b16 {%0,%1}, [%2];"
                    : "=r"(bf[nt][0]), "=r"(bf[nt][1]) : "r"(bd));
            }
#pragma unroll
            for (int mt = 0; mt < 4; mt++)
#pragma unroll
                for (int nt = 0; nt < 4; nt++) {
                    asm volatile(
                        "mma.sync.aligned.m16n8k16.row.col.f32.bf16.bf16.f32 "
                        "{%0,%1,%2,%3}, {%4,%5,%6,%7}, {%8,%9}, {%0,%1,%2,%3};"
                        : "+f"(acc[mt][nt][0]), "+f"(acc[mt][nt][1]),
                          "+f"(acc[mt][nt][2]), "+f"(acc[mt][nt][3])
                        : "r"(af[mt][0]), "r"(af[mt][1]), "r"(af[mt][2]), "r"(af[mt][3]),
                          "r"(bf[nt][0]), "r"(bf[nt][1]));
                }
        }
        CP_WAIT0();
        __syncthreads();
    }

    // ---- epilogue: bias + ELU, fp32 out + bf16 hi/lo into next layer's A ----
#pragma unroll
    for (int nt = 0; nt < 4; nt++) {
        int gc = jb + wn + nt * 8 + (lane & 3) * 2;
        float b0 = bias[gc], b1 = bias[gc + 1];
#pragma unroll
        for (int mt = 0; mt < 4; mt++) {
#pragma unroll
            for (int half = 0; half < 2; half++) {
                int gr = mtile + wm + mt * 16 + (lane >> 2) + half * 8;
                if (gr >= NN) continue;
                float e0 = elu1(acc[mt][nt][half * 2]     + b0);
                float e1 = elu1(acc[mt][nt][half * 2 + 1] + b1);
                *(float2*)&outF[(size_t)gr * HD + gc] = make_float2(e0, e1);
                if (nextA) {
                    __nv_bfloat162 hp = __floats2bfloat162_rn(e0, e1);
                    float r0 = e0 - __low2float(hp), r1 = e1 - __high2float(hp);
                    __nv_bfloat162 lp = __floats2bfloat162_rn(r0, r1);
                    __nv_bfloat16* Ar = nextA + (size_t)gr * KA;
                    *(unsigned*)&Ar[256 + gc] = *(unsigned*)&hp;
                    *(unsigned*)&Ar[768 + gc] = *(unsigned*)&lp;
                }
            }
        }
    }
}

// ---------------- launch ----------------
extern "C" void kernel_launch(void* const* d_in, const int* in_sizes, int n_in,
                              void* d_out, int out_size)
{
    const float* x  = (const float*)d_in[0];
    const void*  ei = d_in[1];
    const float* W[6] = {
        (const float*)d_in[2], (const float*)d_in[3],
        (const float*)d_in[4], (const float*)d_in[5],
        (const float*)d_in[6], (const float*)d_in[7]
    };
    const float* bl1 = (const float*)d_in[8];
    const float* bl2 = (const float*)d_in[9];
    const float* bl3 = (const float*)d_in[10];
    float* out = (float*)d_out;

    void *pA0, *pA1, *pB, *ph1, *ph2;
    cudaGetSymbolAddress(&pA0, g_A0);
    cudaGetSymbolAddress(&pA1, g_A1);
    cudaGetSymbolAddress(&pB,  g_Bw);
    cudaGetSymbolAddress(&ph1, g_h1);
    cudaGetSymbolAddress(&ph2, g_h2);
    __nv_bfloat16* A0 = (__nv_bfloat16*)pA0;
    __nv_bfloat16* A1 = (__nv_bfloat16*)pA1;
    __nv_bfloat16* B  = (__nv_bfloat16*)pB;
    float* h1 = (float*)ph1;
    float* h2 = (float*)ph2;

    cudaFuncSetAttribute(k_gemm_mma, cudaFuncAttributeMaxDynamicSharedMemorySize, SMEM_SZ);

    const int agrid = (NN * 32 + 255) / 256;
    dim3 ggrid(2, MTILES);

    // CSR build with parallel scan
    k_sniff<<<1, 1>>>(ei);
    k_zero_counts<<<(NN + 255) / 256, 256>>>();
    k_hist<<<(NE + 255) / 256, 256>>>(ei);
    k_scan1<<<NBLK, 256>>>();
    k_scan2<<<1, 256>>>();
    k_scan3<<<NBLK, 256>>>();
    k_scatter<<<(NE + 255) / 256, 256>>>(ei);

    for (int l = 0; l < 3; l++)
        k_bprep<<<(256 * 256 + 255) / 256, 256>>>(W[2 * l], W[2 * l + 1], l);

    // layer 1 (aggregate also splits own x rows -> no separate xprep)
    k_aggregate<<<agrid, 256>>>(x, A0, 1);
    k_gemm_mma<<<ggrid, 256, SMEM_SZ>>>(A0, B + 0 * 256 * KB, bl1, h1, A1);
    // layer 2
    k_aggregate<<<agrid, 256>>>(h1, A1, 0);
    k_gemm_mma<<<ggrid, 256, SMEM_SZ>>>(A1, B + 1 * 256 * KB, bl2, h2, A0);
    // layer 3
    k_aggregate<<<agrid, 256>>>(h2, A0, 0);
    k_gemm_mma<<<ggrid, 256, SMEM_SZ>>>(A0, B + 2 * 256 * KB, bl3, out, nullptr);
}